// round 2
// baseline (speedup 1.0000x reference)
#include <cuda_runtime.h>
#include <stdint.h>

#define NROWS 32768   // rows of z_e_x (M)
#define KCOLS 4096    // codebook entries (GEMM N)
#define DDIM  512     // feature dim (GEMM K)

#define BM 128
#define BN 128
#define BK 16
#define TM 8
#define TN 8
#define NTHREADS 256

// scratch for fused argmax: packed (orderable_float<<32) | (KCOLS-1-col)
__device__ unsigned long long g_best[NROWS];

__global__ void init_best_kernel() {
    int i = blockIdx.x * blockDim.x + threadIdx.x;
    if (i < NROWS) g_best[i] = 0ULL;   // 0 == smaller than any real float's key
}

__device__ __forceinline__ unsigned int float_orderable(float f) {
    unsigned int b = __float_as_uint(f);
    return (b & 0x80000000u) ? ~b : (b | 0x80000000u);
}

__global__ __launch_bounds__(NTHREADS)
void gemm_argmax_kernel(const float* __restrict__ A,   // [NROWS, DDIM]
                        const float* __restrict__ B,   // [KCOLS, DDIM]
                        float* __restrict__ C)         // [NROWS, KCOLS]
{
    __shared__ float As[BK][BM];
    __shared__ float Bs[BK][BN];
    __shared__ unsigned long long red[BM][16];

    const int bx = blockIdx.x;  // tile along KCOLS
    const int by = blockIdx.y;  // tile along NROWS
    const int tid = threadIdx.x;
    const int tx = tid & 15;    // 0..15
    const int ty = tid >> 4;    // 0..15

    const float* Ab = A + (size_t)by * BM * DDIM;
    const float* Bb = B + (size_t)bx * BN * DDIM;

    float acc[TM][TN];
#pragma unroll
    for (int i = 0; i < TM; i++)
#pragma unroll
        for (int j = 0; j < TN; j++) acc[i][j] = 0.0f;

    // loader mapping: 512 float4 per tile, 256 threads -> 2 float4 each
    const int lrow = tid >> 2;        // 0..63
    const int lc4  = (tid & 3) * 4;   // 0,4,8,12

    for (int d0 = 0; d0 < DDIM; d0 += BK) {
#pragma unroll
        for (int it = 0; it < 2; it++) {
            int r = lrow + it * 64;
            float4 va = *reinterpret_cast<const float4*>(Ab + (size_t)r * DDIM + d0 + lc4);
            As[lc4 + 0][r] = va.x;
            As[lc4 + 1][r] = va.y;
            As[lc4 + 2][r] = va.z;
            As[lc4 + 3][r] = va.w;
            float4 vb = *reinterpret_cast<const float4*>(Bb + (size_t)r * DDIM + d0 + lc4);
            Bs[lc4 + 0][r] = vb.x;
            Bs[lc4 + 1][r] = vb.y;
            Bs[lc4 + 2][r] = vb.z;
            Bs[lc4 + 3][r] = vb.w;
        }
        __syncthreads();

#pragma unroll
        for (int bk = 0; bk < BK; bk++) {
            float ra[TM], rb[TN];
#pragma unroll
            for (int i = 0; i < TM; i++) ra[i] = As[bk][ty * TM + i];
#pragma unroll
            for (int j = 0; j < TN; j++) rb[j] = Bs[bk][tx * TN + j];
#pragma unroll
            for (int i = 0; i < TM; i++)
#pragma unroll
                for (int j = 0; j < TN; j++)
                    acc[i][j] = fmaf(ra[i], rb[j], acc[i][j]);
        }
        __syncthreads();
    }

    // epilogue: write logits + fused per-row argmax
    const int row0 = by * BM + ty * TM;
    const int col0 = bx * BN + tx * TN;

#pragma unroll
    for (int i = 0; i < TM; i++) {
        int row = row0 + i;
        float* Crow = C + (size_t)row * KCOLS + col0;
        float4 v0 = make_float4(acc[i][0], acc[i][1], acc[i][2], acc[i][3]);
        float4 v1 = make_float4(acc[i][4], acc[i][5], acc[i][6], acc[i][7]);
        *reinterpret_cast<float4*>(Crow)     = v0;
        *reinterpret_cast<float4*>(Crow + 4) = v1;

        // local argmax over this thread's 8 columns
        unsigned long long best = 0ULL;
#pragma unroll
        for (int j = 0; j < TN; j++) {
            unsigned int u = float_orderable(acc[i][j]);
            unsigned long long p =
                ((unsigned long long)u << 32) |
                (unsigned int)(KCOLS - 1 - (col0 + j));   // lower col wins ties
            if (p > best) best = p;
        }
        red[ty * TM + i][tx] = best;
    }
    __syncthreads();

    // reduce 16 partials per row, one atomic per row per block
    if (tid < BM) {
        unsigned long long best = red[tid][0];
#pragma unroll
        for (int t = 1; t < 16; t++) {
            unsigned long long p = red[tid][t];
            if (p > best) best = p;
        }
        atomicMax(&g_best[by * BM + tid], best);
    }
}

__global__ void finalize_kernel(float* __restrict__ out_idx, int count) {
    int n = blockIdx.x * blockDim.x + threadIdx.x;
    if (n < count) {
        unsigned int rev = (unsigned int)(g_best[n] & 0xFFFFFFFFu);
        out_idx[n] = (float)(KCOLS - 1 - rev);
    }
}

extern "C" void kernel_launch(void* const* d_in, const int* in_sizes, int n_in,
                              void* d_out, int out_size) {
    const float* z_e_x    = (const float*)d_in[0];  // [NROWS, DDIM]
    const float* codebook = (const float*)d_in[1];  // [KCOLS, DDIM]
    float* out = (float*)d_out;                      // logits then indices (as float)

    init_best_kernel<<<(NROWS + 255) / 256, 256>>>();

    dim3 grid(KCOLS / BN, NROWS / BM);   // (32, 256)
    gemm_argmax_kernel<<<grid, NTHREADS>>>(z_e_x, codebook, out);

    long long logits_elems = (long long)NROWS * KCOLS;
    if ((long long)out_size >= logits_elems + NROWS) {
        finalize_kernel<<<(NROWS + 255) / 256, 256>>>(out + logits_elems, NROWS);
    }
}

// round 4
// speedup vs baseline: 3.9944x; 3.9944x over previous
#include <cuda_runtime.h>
#include <stdint.h>

#define NROWS 32768   // M
#define KCOLS 4096    // GEMM N (codebook entries)
#define DDIM  512     // reduction K

#define BM 128
#define BN 128
#define BK 32
#define NTILES (DDIM / BK)      // 16
#define NTHREADS 256

#define A_BYTES (BM * BK * 4)               // 16384
#define B_BYTES (BN * BK * 4)               // 16384
#define STAGE_BYTES (A_BYTES + B_BYTES)     // 32768
#define SMEM_TOTAL (2 * STAGE_BYTES)        // 65536

__device__ __forceinline__ uint32_t smem_u32(const void* p) {
    uint32_t a;
    asm("{ .reg .u64 t; cvta.to.shared.u64 t, %1; cvt.u32.u64 %0, t; }" : "=r"(a) : "l"(p));
    return a;
}
__device__ __forceinline__ uint32_t swz(uint32_t off) {   // SW128
    return off ^ ((off >> 3) & 0x70);
}

#define CP_ASYNC16(dst, src) \
    asm volatile("cp.async.cg.shared.global [%0], [%1], 16;" :: "r"(dst), "l"(src) : "memory")

#define LDSM4(r0, r1, r2, r3, addr) \
    asm volatile("ldmatrix.sync.aligned.m8n8.x4.shared.b16 {%0,%1,%2,%3}, [%4];" \
        : "=r"(r0), "=r"(r1), "=r"(r2), "=r"(r3) : "r"(addr))

__device__ __forceinline__ void mma_tf32(float* d, const uint32_t* a, const uint32_t* b) {
    asm volatile(
        "mma.sync.aligned.m16n8k8.row.col.f32.tf32.tf32.f32 "
        "{%0,%1,%2,%3}, {%4,%5,%6,%7}, {%8,%9}, {%0,%1,%2,%3};"
        : "+f"(d[0]), "+f"(d[1]), "+f"(d[2]), "+f"(d[3])
        : "r"(a[0]), "r"(a[1]), "r"(a[2]), "r"(a[3]), "r"(b[0]), "r"(b[1]));
}

__device__ __forceinline__ unsigned int float_orderable(float f) {
    unsigned int b = __float_as_uint(f);
    return (b & 0x80000000u) ? ~b : (b | 0x80000000u);
}

// ---------------------------------------------------------------------------
// TF32 tensor-core GEMM: C[NROWS, KCOLS] = A[NROWS, DDIM] * B[KCOLS, DDIM]^T
// ---------------------------------------------------------------------------
__global__ __launch_bounds__(NTHREADS, 2)
void gemm_tc_kernel(const float* __restrict__ A,
                    const float* __restrict__ B,
                    float* __restrict__ C)
{
    extern __shared__ char smem[];
    const uint32_t smem_base = smem_u32(smem);
    const int tid = threadIdx.x;
    const int lane = tid & 31;
    const int wid = tid >> 5;
    const int wy = wid >> 2;     // 0..1 : M offset wy*64
    const int wx = wid & 3;      // 0..3 : N offset wx*32
    const int bx = blockIdx.x;   // N tile
    const int by = blockIdx.y;   // M tile

    const float* Ab = A + (size_t)by * BM * DDIM;
    const float* Bb = B + (size_t)bx * BN * DDIM;

    // loader mapping: 1024 float4 per operand tile, 256 threads -> 4 each
    const int lrow = tid >> 3;        // 0..31 base row step 32? no: r = i>>3
    const int lc16 = (tid & 7) * 16;  // byte col within 128B row

    float acc[4][4][4];
#pragma unroll
    for (int i = 0; i < 4; i++)
#pragma unroll
        for (int j = 0; j < 4; j++)
#pragma unroll
            for (int q = 0; q < 4; q++) acc[i][j][q] = 0.0f;

    // ldmatrix per-lane address components
    const int rl  = lane & 7;
    const int sel = lane >> 3;          // 0..3 quadrant select
    const int a_row_off = (sel & 1) * 8 + rl;        // + mt*16 + wy*64
    const int a_colw    = (sel >> 1) * 4;            // + ks*8
    const int b_row_off = (sel >> 1) * 8 + rl;       // + p*16 + wx*32
    const int b_colw    = (sel & 1) * 4;             // + ks*8

    auto load_tile = [&](int t, int s) {
        const uint32_t sa = smem_base + s * STAGE_BYTES;
        const uint32_t sb = sa + A_BYTES;
        const int d0 = t * BK;
#pragma unroll
        for (int k = 0; k < 4; k++) {
            int r = lrow + k * 32;
            uint32_t off = swz((uint32_t)(r * 128 + lc16));
            CP_ASYNC16(sa + off, Ab + (size_t)r * DDIM + d0 + (lc16 >> 2));
            CP_ASYNC16(sb + off, Bb + (size_t)r * DDIM + d0 + (lc16 >> 2));
        }
        asm volatile("cp.async.commit_group;" ::: "memory");
    };

    load_tile(0, 0);
    load_tile(1, 1);

    for (int t = 0; t < NTILES; t++) {
        if (t < NTILES - 1) asm volatile("cp.async.wait_group 1;" ::: "memory");
        else                asm volatile("cp.async.wait_group 0;" ::: "memory");
        __syncthreads();

        const int s = t & 1;
        const uint32_t sa = smem_base + s * STAGE_BYTES;
        const uint32_t sb = sa + A_BYTES;

#pragma unroll
        for (int ks = 0; ks < 4; ks++) {
            const int k0w = ks * 8;
            uint32_t af[4][4], bf[4][2];
#pragma unroll
            for (int mt = 0; mt < 4; mt++) {
                uint32_t off = (uint32_t)((wy * 64 + mt * 16 + a_row_off) * 128 +
                                          (k0w + a_colw) * 4);
                LDSM4(af[mt][0], af[mt][1], af[mt][2], af[mt][3], sa + swz(off));
            }
#pragma unroll
            for (int p = 0; p < 2; p++) {
                uint32_t off = (uint32_t)((wx * 32 + p * 16 + b_row_off) * 128 +
                                          (k0w + b_colw) * 4);
                uint32_t r0, r1, r2, r3;
                LDSM4(r0, r1, r2, r3, sb + swz(off));
                bf[p * 2][0] = r0;     bf[p * 2][1] = r1;
                bf[p * 2 + 1][0] = r2; bf[p * 2 + 1][1] = r3;
            }
#pragma unroll
            for (int mt = 0; mt < 4; mt++)
#pragma unroll
                for (int nt = 0; nt < 4; nt++)
                    mma_tf32(acc[mt][nt], af[mt], bf[nt]);
        }
        __syncthreads();
        if (t + 2 < NTILES) load_tile(t + 2, s);
    }

    // epilogue: write logits
    const int row_base = by * BM + wy * 64 + (lane >> 2);
    const int col_base = bx * BN + wx * 32 + (lane & 3) * 2;
#pragma unroll
    for (int mt = 0; mt < 4; mt++) {
        int r0 = row_base + mt * 16;
        float* C0 = C + (size_t)r0 * KCOLS + col_base;
        float* C1 = C + (size_t)(r0 + 8) * KCOLS + col_base;
#pragma unroll
        for (int nt = 0; nt < 4; nt++) {
            *reinterpret_cast<float2*>(C0 + nt * 8) =
                make_float2(acc[mt][nt][0], acc[mt][nt][1]);
            *reinterpret_cast<float2*>(C1 + nt * 8) =
                make_float2(acc[mt][nt][2], acc[mt][nt][3]);
        }
    }
}

// ---------------------------------------------------------------------------
// Exact argmax: scan tf32 logits row for max, gather candidates within a
// threshold that provably contains the true fp32 argmax, recompute exactly.
// ---------------------------------------------------------------------------
__global__ __launch_bounds__(256)
void fixup_kernel(const float* __restrict__ A, const float* __restrict__ B,
                  const float* __restrict__ C, float* __restrict__ out_idx)
{
    const int n = (blockIdx.x * blockDim.x + threadIdx.x) >> 5;   // row per warp
    const int lane = threadIdx.x & 31;
    if (n >= NROWS) return;

    const float4* Crow = reinterpret_cast<const float4*>(C + (size_t)n * KCOLS);

    // pass 1: tf32 row max
    float m = -3.4e38f;
#pragma unroll 8
    for (int i = 0; i < 32; i++) {
        float4 v = Crow[i * 32 + lane];
        m = fmaxf(m, fmaxf(fmaxf(v.x, v.y), fmaxf(v.z, v.w)));
    }
#pragma unroll
    for (int off = 16; off; off >>= 1)
        m = fmaxf(m, __shfl_xor_sync(0xffffffffu, m, off));

    const float thr = m - 5e-4f;   // >> 2x max tf32-truncation error bound

    // pass 2: candidate columns (L1-resident re-read)
    int cand[16];
    int nc = 0;
#pragma unroll 4
    for (int i = 0; i < 32; i++) {
        int f4 = i * 32 + lane;
        float4 v = Crow[f4];
        int c0 = f4 * 4;
        if (v.x >= thr && nc < 16) cand[nc++] = c0;
        if (v.y >= thr && nc < 16) cand[nc++] = c0 + 1;
        if (v.z >= thr && nc < 16) cand[nc++] = c0 + 2;
        if (v.w >= thr && nc < 16) cand[nc++] = c0 + 3;
    }

    // exact fp32 recompute of all candidates (warp-cooperative dots)
    const float4* z4 = reinterpret_cast<const float4*>(A + (size_t)n * DDIM) + lane * 4;
    unsigned long long best = 0ULL;

    for (int l = 0; l < 32; l++) {
        int cnt = __shfl_sync(0xffffffffu, nc, l);
        for (int j = 0; j < cnt; j++) {
            int mycol = (j < 16) ? cand[j] : 0;
            int col = __shfl_sync(0xffffffffu, mycol, l);
            const float4* c4 = reinterpret_cast<const float4*>(B + (size_t)col * DDIM) + lane * 4;
            float sum = 0.0f;
#pragma unroll
            for (int q = 0; q < 4; q++) {
                float4 a = z4[q], b = c4[q];
                sum = fmaf(a.x, b.x, sum);
                sum = fmaf(a.y, b.y, sum);
                sum = fmaf(a.z, b.z, sum);
                sum = fmaf(a.w, b.w, sum);
            }
#pragma unroll
            for (int off = 16; off; off >>= 1)
                sum += __shfl_xor_sync(0xffffffffu, sum, off);
            unsigned long long p = ((unsigned long long)float_orderable(sum) << 32) |
                                   (unsigned int)(KCOLS - 1 - col);   // lower col wins ties
            if (p > best) best = p;
        }
    }
    if (lane == 0)
        out_idx[n] = (float)(KCOLS - 1 - (unsigned int)(best & 0xFFFFFFFFu));
}

extern "C" void kernel_launch(void* const* d_in, const int* in_sizes, int n_in,
                              void* d_out, int out_size) {
    const float* z_e_x    = (const float*)d_in[0];  // [NROWS, DDIM]
    const float* codebook = (const float*)d_in[1];  // [KCOLS, DDIM]
    float* out = (float*)d_out;                      // logits then indices

    cudaFuncSetAttribute(gemm_tc_kernel, cudaFuncAttributeMaxDynamicSharedMemorySize, SMEM_TOTAL);

    dim3 grid(KCOLS / BN, NROWS / BM);   // (32, 256), x fastest -> A-tile L2 reuse
    gemm_tc_kernel<<<grid, NTHREADS, SMEM_TOTAL>>>(z_e_x, codebook, out);

    long long logits_elems = (long long)NROWS * KCOLS;
    if ((long long)out_size >= logits_elems + NROWS) {
        fixup_kernel<<<NROWS / 8, 256>>>(z_e_x, codebook, out, out + logits_elems);
    }
}

// round 5
// speedup vs baseline: 4.6262x; 1.1582x over previous
#include <cuda_runtime.h>
#include <stdint.h>

#define NROWS 32768   // M
#define KCOLS 4096    // GEMM N (codebook entries)
#define DDIM  512     // reduction K

#define BM 128
#define BN 128
#define BK 32
#define NTILES (DDIM / BK)      // 16
#define NXTILES (KCOLS / BN)    // 32
#define NTHREADS 256

#define A_BYTES (BM * BK * 4)               // 16384
#define B_BYTES (BN * BK * 4)               // 16384
#define STAGE_BYTES (A_BYTES + B_BYTES)     // 32768
#define SMEM_TOTAL (2 * STAGE_BYTES)        // 65536

// per-(row, N-tile) max of tf32 logits, as orderable uint. 4MB. Fully written
// by the GEMM epilogue every launch -> no init kernel needed.
__device__ unsigned int g_tilemax[NROWS * NXTILES];

__device__ __forceinline__ uint32_t smem_u32(const void* p) {
    uint32_t a;
    asm("{ .reg .u64 t; cvta.to.shared.u64 t, %1; cvt.u32.u64 %0, t; }" : "=r"(a) : "l"(p));
    return a;
}
__device__ __forceinline__ uint32_t swz(uint32_t off) {   // SW128
    return off ^ ((off >> 3) & 0x70);
}

#define CP_ASYNC16(dst, src) \
    asm volatile("cp.async.cg.shared.global [%0], [%1], 16;" :: "r"(dst), "l"(src) : "memory")

#define LDSM4(r0, r1, r2, r3, addr) \
    asm volatile("ldmatrix.sync.aligned.m8n8.x4.shared.b16 {%0,%1,%2,%3}, [%4];" \
        : "=r"(r0), "=r"(r1), "=r"(r2), "=r"(r3) : "r"(addr))

__device__ __forceinline__ void mma_tf32(float* d, const uint32_t* a, const uint32_t* b) {
    asm volatile(
        "mma.sync.aligned.m16n8k8.row.col.f32.tf32.tf32.f32 "
        "{%0,%1,%2,%3}, {%4,%5,%6,%7}, {%8,%9}, {%0,%1,%2,%3};"
        : "+f"(d[0]), "+f"(d[1]), "+f"(d[2]), "+f"(d[3])
        : "r"(a[0]), "r"(a[1]), "r"(a[2]), "r"(a[3]), "r"(b[0]), "r"(b[1]));
}

__device__ __forceinline__ unsigned int float_orderable(float f) {
    unsigned int b = __float_as_uint(f);
    return (b & 0x80000000u) ? ~b : (b | 0x80000000u);
}
__device__ __forceinline__ float orderable_to_float(unsigned int u) {
    return (u & 0x80000000u) ? __uint_as_float(u ^ 0x80000000u) : __uint_as_float(~u);
}

// ---------------------------------------------------------------------------
// TF32 tensor-core GEMM: C[NROWS, KCOLS] = A[NROWS, DDIM] * B[KCOLS, DDIM]^T
// Epilogue also reduces per-row tile maxima into g_tilemax.
// ---------------------------------------------------------------------------
__global__ __launch_bounds__(NTHREADS, 2)
void gemm_tc_kernel(const float* __restrict__ A,
                    const float* __restrict__ B,
                    float* __restrict__ C)
{
    extern __shared__ char smem[];
    __shared__ unsigned int sMax[BM];
    const uint32_t smem_base = smem_u32(smem);
    const int tid = threadIdx.x;
    const int lane = tid & 31;
    const int wid = tid >> 5;
    const int wy = wid >> 2;     // 0..1 : M offset wy*64
    const int wx = wid & 3;      // 0..3 : N offset wx*32
    const int bx = blockIdx.x;   // N tile
    const int by = blockIdx.y;   // M tile

    if (tid < BM) sMax[tid] = 0u;

    const float* Ab = A + (size_t)by * BM * DDIM;
    const float* Bb = B + (size_t)bx * BN * DDIM;

    const int lrow = tid >> 3;
    const int lc16 = (tid & 7) * 16;

    float acc[4][4][4];
#pragma unroll
    for (int i = 0; i < 4; i++)
#pragma unroll
        for (int j = 0; j < 4; j++)
#pragma unroll
            for (int q = 0; q < 4; q++) acc[i][j][q] = 0.0f;

    const int rl  = lane & 7;
    const int sel = lane >> 3;
    const int a_row_off = (sel & 1) * 8 + rl;
    const int a_colw    = (sel >> 1) * 4;
    const int b_row_off = (sel >> 1) * 8 + rl;
    const int b_colw    = (sel & 1) * 4;

    auto load_tile = [&](int t, int s) {
        const uint32_t sa = smem_base + s * STAGE_BYTES;
        const uint32_t sb = sa + A_BYTES;
        const int d0 = t * BK;
#pragma unroll
        for (int k = 0; k < 4; k++) {
            int r = lrow + k * 32;
            uint32_t off = swz((uint32_t)(r * 128 + lc16));
            CP_ASYNC16(sa + off, Ab + (size_t)r * DDIM + d0 + (lc16 >> 2));
            CP_ASYNC16(sb + off, Bb + (size_t)r * DDIM + d0 + (lc16 >> 2));
        }
        asm volatile("cp.async.commit_group;" ::: "memory");
    };

    load_tile(0, 0);
    load_tile(1, 1);

    for (int t = 0; t < NTILES; t++) {
        if (t < NTILES - 1) asm volatile("cp.async.wait_group 1;" ::: "memory");
        else                asm volatile("cp.async.wait_group 0;" ::: "memory");
        __syncthreads();

        const int s = t & 1;
        const uint32_t sa = smem_base + s * STAGE_BYTES;
        const uint32_t sb = sa + A_BYTES;

#pragma unroll
        for (int ks = 0; ks < 4; ks++) {
            const int k0w = ks * 8;
            uint32_t af[4][4], bf[4][2];
#pragma unroll
            for (int mt = 0; mt < 4; mt++) {
                uint32_t off = (uint32_t)((wy * 64 + mt * 16 + a_row_off) * 128 +
                                          (k0w + a_colw) * 4);
                LDSM4(af[mt][0], af[mt][1], af[mt][2], af[mt][3], sa + swz(off));
            }
#pragma unroll
            for (int p = 0; p < 2; p++) {
                uint32_t off = (uint32_t)((wx * 32 + p * 16 + b_row_off) * 128 +
                                          (k0w + b_colw) * 4);
                uint32_t r0, r1, r2, r3;
                LDSM4(r0, r1, r2, r3, sb + swz(off));
                bf[p * 2][0] = r0;     bf[p * 2][1] = r1;
                bf[p * 2 + 1][0] = r2; bf[p * 2 + 1][1] = r3;
            }
#pragma unroll
            for (int mt = 0; mt < 4; mt++)
#pragma unroll
                for (int nt = 0; nt < 4; nt++)
                    mma_tf32(acc[mt][nt], af[mt], bf[nt]);
        }
        __syncthreads();
        if (t + 2 < NTILES) load_tile(t + 2, s);
    }

    // ---- epilogue: write logits + per-row tile max ----
    const int row_base = by * BM + wy * 64 + (lane >> 2);
    const int col_base = bx * BN + wx * 32 + (lane & 3) * 2;
#pragma unroll
    for (int mt = 0; mt < 4; mt++) {
        int r0 = row_base + mt * 16;
        float* C0 = C + (size_t)r0 * KCOLS + col_base;
        float* C1 = C + (size_t)(r0 + 8) * KCOLS + col_base;
        float mx0 = -3.4e38f, mx1 = -3.4e38f;
#pragma unroll
        for (int nt = 0; nt < 4; nt++) {
            *reinterpret_cast<float2*>(C0 + nt * 8) =
                make_float2(acc[mt][nt][0], acc[mt][nt][1]);
            *reinterpret_cast<float2*>(C1 + nt * 8) =
                make_float2(acc[mt][nt][2], acc[mt][nt][3]);
            mx0 = fmaxf(mx0, fmaxf(acc[mt][nt][0], acc[mt][nt][1]));
            mx1 = fmaxf(mx1, fmaxf(acc[mt][nt][2], acc[mt][nt][3]));
        }
        // reduce across the 4 lanes sharing each row (lane & 3)
        mx0 = fmaxf(mx0, __shfl_xor_sync(0xffffffffu, mx0, 1));
        mx0 = fmaxf(mx0, __shfl_xor_sync(0xffffffffu, mx0, 2));
        mx1 = fmaxf(mx1, __shfl_xor_sync(0xffffffffu, mx1, 1));
        mx1 = fmaxf(mx1, __shfl_xor_sync(0xffffffffu, mx1, 2));
        if ((lane & 3) == 0) {
            int rl0 = wy * 64 + mt * 16 + (lane >> 2);
            atomicMax(&sMax[rl0],     float_orderable(mx0));
            atomicMax(&sMax[rl0 + 8], float_orderable(mx1));
        }
    }
    __syncthreads();
    if (tid < BM)
        g_tilemax[(size_t)(by * BM + tid) * NXTILES + bx] = sMax[tid];
}

// ---------------------------------------------------------------------------
// Exact argmax from tile maxima: select near-max tiles, load only those
// logits, recompute candidates exactly in fp32. One warp per row.
// ---------------------------------------------------------------------------
__global__ __launch_bounds__(256)
void argmax_kernel(const float* __restrict__ A, const float* __restrict__ B,
                   const float* __restrict__ C, float* __restrict__ out_idx)
{
    const int n = (blockIdx.x * blockDim.x + threadIdx.x) >> 5;   // row per warp
    const int lane = threadIdx.x & 31;
    if (n >= NROWS) return;

    // lane t holds tile t's max (NXTILES == 32)
    const unsigned int tm = g_tilemax[(size_t)n * NXTILES + lane];
    unsigned int gm = tm;
#pragma unroll
    for (int off = 16; off; off >>= 1)
        gm = max(gm, __shfl_xor_sync(0xffffffffu, gm, off));

    const float fmx = orderable_to_float(gm);
    const float thr = fmx - 5e-4f;                 // >> 30x max tf32 error
    const unsigned int thr_ord = float_orderable(thr);

    unsigned int tilemask = __ballot_sync(0xffffffffu, tm >= thr_ord);

    const float4* Crow = reinterpret_cast<const float4*>(C + (size_t)n * KCOLS);
    int cand[8];
    int nc = 0;
    while (tilemask) {
        int tile = __ffs(tilemask) - 1;
        tilemask &= tilemask - 1;
        float4 v = Crow[tile * 32 + lane];
        int c0 = tile * BN + lane * 4;
        if (v.x >= thr && nc < 8) cand[nc++] = c0;
        if (v.y >= thr && nc < 8) cand[nc++] = c0 + 1;
        if (v.z >= thr && nc < 8) cand[nc++] = c0 + 2;
        if (v.w >= thr && nc < 8) cand[nc++] = c0 + 3;
    }

    // exact fp32 recompute of all candidates (warp-cooperative dots)
    const float4* z4 = reinterpret_cast<const float4*>(A + (size_t)n * DDIM) + lane * 4;
    unsigned long long best = 0ULL;

    for (int l = 0; l < 32; l++) {
        int cnt = __shfl_sync(0xffffffffu, nc, l);
        for (int j = 0; j < cnt; j++) {
            int mycol = (j < 8) ? cand[j] : 0;
            int col = __shfl_sync(0xffffffffu, mycol, l);
            const float4* c4 = reinterpret_cast<const float4*>(B + (size_t)col * DDIM) + lane * 4;
            float sum = 0.0f;
#pragma unroll
            for (int q = 0; q < 4; q++) {
                float4 a = z4[q], b = c4[q];
                sum = fmaf(a.x, b.x, sum);
                sum = fmaf(a.y, b.y, sum);
                sum = fmaf(a.z, b.z, sum);
                sum = fmaf(a.w, b.w, sum);
            }
#pragma unroll
            for (int off = 16; off; off >>= 1)
                sum += __shfl_xor_sync(0xffffffffu, sum, off);
            unsigned long long p = ((unsigned long long)float_orderable(sum) << 32) |
                                   (unsigned int)(KCOLS - 1 - col);   // lower col wins ties
            if (p > best) best = p;
        }
    }
    if (lane == 0)
        out_idx[n] = (float)(KCOLS - 1 - (unsigned int)(best & 0xFFFFFFFFu));
}

extern "C" void kernel_launch(void* const* d_in, const int* in_sizes, int n_in,
                              void* d_out, int out_size) {
    const float* z_e_x    = (const float*)d_in[0];  // [NROWS, DDIM]
    const float* codebook = (const float*)d_in[1];  // [KCOLS, DDIM]
    float* out = (float*)d_out;                      // logits then indices

    cudaFuncSetAttribute(gemm_tc_kernel, cudaFuncAttributeMaxDynamicSharedMemorySize, SMEM_TOTAL);

    dim3 grid(KCOLS / BN, NROWS / BM);   // (32, 256), x fastest -> A-tile L2 reuse
    gemm_tc_kernel<<<grid, NTHREADS, SMEM_TOTAL>>>(z_e_x, codebook, out);

    long long logits_elems = (long long)NROWS * KCOLS;
    if ((long long)out_size >= logits_elems + NROWS) {
        argmax_kernel<<<NROWS / 8, 256>>>(z_e_x, codebook, out, out + logits_elems);
    }
}